// round 1
// baseline (speedup 1.0000x reference)
#include <cuda_runtime.h>
#include <cstdint>

#define KN 100000   // batch nodes
#define ME 600000   // edges

// ---------------- scratch (device globals: no allocations allowed) ----------
__device__ float g_y[(size_t)KN * 512];   // per node: [q(128) | k(128) | v(128) | skip(128)]
__device__ float g_e[(size_t)ME * 128];   // per edge: e = edge_attr @ We
__device__ float g_lu[KN];                // last_update gathered by n_id
__device__ float g_denom[KN * 2];         // softmax denominator per (node, head)

// ---------------- helpers ---------------------------------------------------
__device__ __forceinline__ float fast_cos(float x) {
    // Cody-Waite range reduction then MUFU cos: accurate to ~1e-6 abs for |x| < ~1e4
    float n = rintf(x * 0.15915494309189535f);
    float r = fmaf(n, -6.28125f, x);
    r = fmaf(n, -1.9353071795864769e-3f, r);
    return __cosf(r);
}

__device__ __forceinline__ unsigned long long dupf(float a) {
    unsigned long long u;
    asm("mov.b64 %0, {%1,%1};" : "=l"(u) : "f"(a));
    return u;
}
__device__ __forceinline__ float2 u2f(unsigned long long u) {
    float2 f;
    asm("mov.b64 {%0,%1}, %2;" : "=f"(f.x), "=f"(f.y) : "l"(u));
    return f;
}
__device__ __forceinline__ void ffma2(unsigned long long& acc, unsigned long long a, unsigned long long b) {
    asm("fma.rn.f32x2 %0, %1, %2, %0;" : "+l"(acc) : "l"(a), "l"(b));
}

// ---------------- init: zero out/denom, gather last_update ------------------
__global__ void k_init(float* __restrict__ out,
                       const float* __restrict__ last_update,
                       const int* __restrict__ n_id) {
    int i = blockIdx.x * 256 + threadIdx.x;
    if (i < KN * 128) out[i] = 0.f;
    if (i < KN * 2) g_denom[i] = 0.f;
    if (i < KN) g_lu[i] = last_update[n_id[i]];
}

// ---------------- node GEMM: y[:,which*128:+128] = [mem||feat] @ W + b ------
struct NodeW { const float* W[4]; const float* b[4]; };

__global__ __launch_bounds__(256) void k_node_gemm(const int* __restrict__ n_id,
                                                   const float* __restrict__ memv,
                                                   const float* __restrict__ feat,
                                                   NodeW p) {
    __shared__ float As[16][64];
    __shared__ float Bs[16][128];
    __shared__ int nid_s[64];
    const int which = blockIdx.y;
    const float* __restrict__ W = p.W[which];
    const float* __restrict__ bias = p.b[which];
    const int m0 = blockIdx.x * 64;
    const int tid = threadIdx.x;
    int rows = KN - m0; if (rows > 64) rows = 64;
    if (tid < 64) nid_s[tid] = n_id[m0 + (tid < rows ? tid : 0)];
    __syncthreads();

    const int tm = tid >> 4, tn = tid & 15;   // C subtile: 4 rows x 8 cols
    const int am = tid & 63, akq = tid >> 6;  // A-build mapping
    unsigned long long acc[4][4];
#pragma unroll
    for (int r = 0; r < 4; r++)
#pragma unroll
        for (int j = 0; j < 4; j++) acc[r][j] = 0ull;

    for (int kc = 0; kc < 256; kc += 16) {
        // build A tile (gathered x = memory || node_feat)
        {
            int c = kc + akq * 4;
            int nid = nid_s[am];
            float4 av;
            if (c < 128) av = *(const float4*)&memv[(size_t)nid * 128 + c];
            else         av = *(const float4*)&feat[(size_t)nid * 128 + (c - 128)];
            As[akq * 4 + 0][am] = av.x;
            As[akq * 4 + 1][am] = av.y;
            As[akq * 4 + 2][am] = av.z;
            As[akq * 4 + 3][am] = av.w;
        }
        // load B tile
        {
            int k = tid >> 4, n = (tid & 15) * 8;
            const float4* s4 = (const float4*)&W[(kc + k) * 128 + n];
            *(float4*)&Bs[k][n] = s4[0];
            *(float4*)&Bs[k][n + 4] = s4[1];
        }
        __syncthreads();
#pragma unroll
        for (int k = 0; k < 16; k++) {
            float4 a4 = *(const float4*)&As[k][tm * 4];
            unsigned long long a2[4] = { dupf(a4.x), dupf(a4.y), dupf(a4.z), dupf(a4.w) };
            const unsigned long long* bp = (const unsigned long long*)&Bs[k][tn * 8];
            unsigned long long b2[4] = { bp[0], bp[1], bp[2], bp[3] };
#pragma unroll
            for (int r = 0; r < 4; r++)
#pragma unroll
                for (int j = 0; j < 4; j++) ffma2(acc[r][j], a2[r], b2[j]);
        }
        __syncthreads();
    }

    float4 bb0 = *(const float4*)&bias[tn * 8];
    float4 bb1 = *(const float4*)&bias[tn * 8 + 4];
#pragma unroll
    for (int r = 0; r < 4; r++) {
        int rl = tm * 4 + r;
        if (rl < rows) {
            float2 f0 = u2f(acc[r][0]), f1 = u2f(acc[r][1]), f2 = u2f(acc[r][2]), f3 = u2f(acc[r][3]);
            float4 o0 = make_float4(f0.x + bb0.x, f0.y + bb0.y, f1.x + bb0.z, f1.y + bb0.w);
            float4 o1 = make_float4(f2.x + bb1.x, f2.y + bb1.y, f3.x + bb1.z, f3.y + bb1.w);
            float* dst = &g_y[(size_t)(m0 + rl) * 512 + which * 128 + tn * 8];
            *(float4*)&dst[0] = o0;
            *(float4*)&dst[4] = o1;
        }
    }
}

// ---------------- edge GEMM: e = [cos(rel_t*w+b) || msg] @ We ---------------
__global__ __launch_bounds__(256) void k_edge_gemm(const int* __restrict__ src_a,
                                                   const int* __restrict__ e_id,
                                                   const float* __restrict__ edge_t,
                                                   const float* __restrict__ eraw,
                                                   const float* __restrict__ w_t,
                                                   const float* __restrict__ b_t,
                                                   const float* __restrict__ We) {
    __shared__ float As[16][64];
    __shared__ float Bs[16][128];
    __shared__ float relt_s[64];
    __shared__ int eid_s[64];
    const int m0 = blockIdx.x * 64;
    const int tid = threadIdx.x;
    if (tid < 64) {
        int e = e_id[m0 + tid];
        eid_s[tid] = e;
        relt_s[tid] = edge_t[e] - g_lu[src_a[m0 + tid]];
    }
    __syncthreads();

    const int tm = tid >> 4, tn = tid & 15;
    const int am = tid & 63, akq = tid >> 6;
    unsigned long long acc[4][4];
#pragma unroll
    for (int r = 0; r < 4; r++)
#pragma unroll
        for (int j = 0; j < 4; j++) acc[r][j] = 0ull;

    for (int kc = 0; kc < 256; kc += 16) {
        {
            int c = kc + akq * 4;
            float4 av;
            if (c < 128) {
                float rt = relt_s[am];
                float4 w = *(const float4*)&w_t[c];
                float4 b = *(const float4*)&b_t[c];
                av.x = fast_cos(fmaf(rt, w.x, b.x));
                av.y = fast_cos(fmaf(rt, w.y, b.y));
                av.z = fast_cos(fmaf(rt, w.z, b.z));
                av.w = fast_cos(fmaf(rt, w.w, b.w));
            } else {
                av = *(const float4*)&eraw[(size_t)eid_s[am] * 128 + (c - 128)];
            }
            As[akq * 4 + 0][am] = av.x;
            As[akq * 4 + 1][am] = av.y;
            As[akq * 4 + 2][am] = av.z;
            As[akq * 4 + 3][am] = av.w;
        }
        {
            int k = tid >> 4, n = (tid & 15) * 8;
            const float4* s4 = (const float4*)&We[(kc + k) * 128 + n];
            *(float4*)&Bs[k][n] = s4[0];
            *(float4*)&Bs[k][n + 4] = s4[1];
        }
        __syncthreads();
#pragma unroll
        for (int k = 0; k < 16; k++) {
            float4 a4 = *(const float4*)&As[k][tm * 4];
            unsigned long long a2[4] = { dupf(a4.x), dupf(a4.y), dupf(a4.z), dupf(a4.w) };
            const unsigned long long* bp = (const unsigned long long*)&Bs[k][tn * 8];
            unsigned long long b2[4] = { bp[0], bp[1], bp[2], bp[3] };
#pragma unroll
            for (int r = 0; r < 4; r++)
#pragma unroll
                for (int j = 0; j < 4; j++) ffma2(acc[r][j], a2[r], b2[j]);
        }
        __syncthreads();
    }

#pragma unroll
    for (int r = 0; r < 4; r++) {
        int row = m0 + tm * 4 + r;
        float2 f0 = u2f(acc[r][0]), f1 = u2f(acc[r][1]), f2 = u2f(acc[r][2]), f3 = u2f(acc[r][3]);
        float4 o0 = make_float4(f0.x, f0.y, f1.x, f1.y);
        float4 o1 = make_float4(f2.x, f2.y, f3.x, f3.y);
        float* dst = &g_e[(size_t)row * 128 + tn * 8];
        *(float4*)&dst[0] = o0;
        *(float4*)&dst[4] = o1;
    }
}

// ---------------- fused attention: alpha = exp(q.(k+e)/8); accumulate -------
// No max-subtraction: |alpha_raw| is O(0.1) for this data, exp is safe, and
// softmax is invariant to the shift, so results match the reference.
__global__ __launch_bounds__(256) void k_attn(const int* __restrict__ src_a,
                                              const int* __restrict__ dst_a,
                                              float* __restrict__ out) {
    int gw = (blockIdx.x * 256 + threadIdx.x) >> 5;
    int lane = threadIdx.x & 31;
    if (gw >= ME) return;
    int s = src_a[gw], d = dst_a[gw];
    const float4* qy = (const float4*)&g_y[(size_t)d * 512];
    const float4* ky = (const float4*)&g_y[(size_t)s * 512 + 128];
    const float4* vy = (const float4*)&g_y[(size_t)s * 512 + 256];
    const float4* ep = (const float4*)&g_e[(size_t)gw * 128];
    float4 q4 = qy[lane], k4 = ky[lane], v4 = vy[lane], e4 = ep[lane];
    float4 ke = make_float4(k4.x + e4.x, k4.y + e4.y, k4.z + e4.z, k4.w + e4.w);
    float p = q4.x * ke.x + q4.y * ke.y + q4.z * ke.z + q4.w * ke.w;
    // butterfly reduce within each 16-lane half (one head per half-warp)
    p += __shfl_xor_sync(0xffffffffu, p, 8);
    p += __shfl_xor_sync(0xffffffffu, p, 4);
    p += __shfl_xor_sync(0xffffffffu, p, 2);
    p += __shfl_xor_sync(0xffffffffu, p, 1);
    float alpha = __expf(p * 0.125f);   // 1/sqrt(64)
    if ((lane & 15) == 0) atomicAdd(&g_denom[d * 2 + (lane >> 4)], alpha);
    float4 o = make_float4(alpha * (v4.x + e4.x), alpha * (v4.y + e4.y),
                           alpha * (v4.z + e4.z), alpha * (v4.w + e4.w));
    float* dptr = &out[(size_t)d * 128 + lane * 4];
    asm volatile("red.global.add.v4.f32 [%0], {%1,%2,%3,%4};"
                 :: "l"(dptr), "f"(o.x), "f"(o.y), "f"(o.z), "f"(o.w) : "memory");
}

// ---------------- finalize: out = out/denom + skip --------------------------
__global__ void k_final(float* __restrict__ out) {
    int i = blockIdx.x * 256 + threadIdx.x;   // one float4 per thread
    if (i >= KN * 32) return;
    int node = i >> 5;
    int j4 = (i & 31) * 4;
    int h = j4 >> 6;
    float den = g_denom[node * 2 + h];
    float inv = den > 0.f ? 1.f / den : 0.f;
    float4 u = *(float4*)&out[(size_t)node * 128 + j4];
    float4 sk = *(const float4*)&g_y[(size_t)node * 512 + 384 + j4];
    u.x = u.x * inv + sk.x;
    u.y = u.y * inv + sk.y;
    u.z = u.z * inv + sk.z;
    u.w = u.w * inv + sk.w;
    *(float4*)&out[(size_t)node * 128 + j4] = u;
}

// ---------------- launch -----------------------------------------------------
extern "C" void kernel_launch(void* const* d_in, const int* in_sizes, int n_in,
                              void* d_out, int out_size) {
    (void)in_sizes; (void)n_in; (void)out_size;
    const int*   n_id    = (const int*)d_in[0];
    const int*   eib     = (const int*)d_in[1];   // [2, M]: src then dst
    const int*   e_id    = (const int*)d_in[2];
    // d_in[3] t_targets unused by reference
    const float* nfeat   = (const float*)d_in[4];
    const float* eraw    = (const float*)d_in[5];
    const float* edge_t  = (const float*)d_in[6];
    const float* memv    = (const float*)d_in[7];
    const float* last_up = (const float*)d_in[8];
    const float* w_t     = (const float*)d_in[9];
    const float* b_t     = (const float*)d_in[10];
    NodeW p;
    p.W[0] = (const float*)d_in[11]; p.b[0] = (const float*)d_in[12];  // q
    p.W[1] = (const float*)d_in[13]; p.b[1] = (const float*)d_in[14];  // k
    p.W[2] = (const float*)d_in[15]; p.b[2] = (const float*)d_in[16];  // v
    const float* We = (const float*)d_in[17];
    p.W[3] = (const float*)d_in[18]; p.b[3] = (const float*)d_in[19];  // skip
    float* out = (float*)d_out;

    k_init<<<(KN * 128 + 255) / 256, 256>>>(out, last_up, n_id);
    dim3 gn((KN + 63) / 64, 4);
    k_node_gemm<<<gn, 256>>>(n_id, memv, nfeat, p);
    k_edge_gemm<<<ME / 64, 256>>>(eib, e_id, edge_t, eraw, w_t, b_t, We);
    k_attn<<<ME / 8, 256>>>(eib, eib + ME, out);
    k_final<<<(KN * 32 + 255) / 256, 256>>>(out);
}

// round 2
// speedup vs baseline: 1.7315x; 1.7315x over previous
#include <cuda_runtime.h>
#include <cstdint>

#define KN 100000   // batch nodes
#define ME 600000   // edges

// ---------------- scratch (device globals: no allocations allowed) ----------
__device__ float g_y[(size_t)KN * 512];   // per node: [q(128) | k(128) | v(128) | skip(128)]
__device__ float g_e[(size_t)ME * 128];   // per edge: e = edge_attr @ We
__device__ float g_lu[KN];                // last_update gathered by n_id
__device__ float g_denom[KN * 2];         // softmax denominator per (node, head)

// ---------------- helpers ---------------------------------------------------
__device__ __forceinline__ float fast_cos(float x) {
    float n = rintf(x * 0.15915494309189535f);
    float r = fmaf(n, -6.28125f, x);
    r = fmaf(n, -1.9353071795864769e-3f, r);
    return __cosf(r);
}
__device__ __forceinline__ unsigned long long dupf(float a) {
    unsigned long long u;
    asm("mov.b64 %0, {%1,%1};" : "=l"(u) : "f"(a));
    return u;
}
__device__ __forceinline__ float2 u2f(unsigned long long u) {
    float2 f;
    asm("mov.b64 {%0,%1}, %2;" : "=f"(f.x), "=f"(f.y) : "l"(u));
    return f;
}
__device__ __forceinline__ void ffma2(unsigned long long& acc, unsigned long long a, unsigned long long b) {
    asm("fma.rn.f32x2 %0, %1, %2, %0;" : "+l"(acc) : "l"(a), "l"(b));
}

// ---------------- init: zero out/denom, gather last_update ------------------
__global__ void k_init(float* __restrict__ out,
                       const float* __restrict__ last_update,
                       const int* __restrict__ n_id) {
    int i = blockIdx.x * 256 + threadIdx.x;
    if (i < KN * 128) out[i] = 0.f;
    if (i < KN * 2) g_denom[i] = 0.f;
    if (i < KN) g_lu[i] = last_update[n_id[i]];
}

// ============================================================================
// GEMM tiling: BM=128, BN=128, BK=16, 256 threads, 8x8 outputs per thread.
// Warps 4x2 (wm 0..3, wn 0..1); lanes 4x8 (lm, ln).
// Thread C-tile: rows wm*32+lm*8 .. +8, cols wn*64+ln*8 .. +8.
// ============================================================================

struct NodeW { const float* W[4]; const float* b[4]; };

__global__ __launch_bounds__(256, 2) void k_node_gemm(const int* __restrict__ n_id,
                                                      const float* __restrict__ memv,
                                                      const float* __restrict__ feat,
                                                      NodeW p) {
    __shared__ float As[16][128];
    __shared__ float Bs[16][128];
    __shared__ int nid_s[128];
    const int which = blockIdx.x;
    const float* __restrict__ W = p.W[which];
    const float* __restrict__ bias = p.b[which];
    const int m0 = blockIdx.y * 128;
    const int tid = threadIdx.x;
    int rows = KN - m0; if (rows > 128) rows = 128;
    if (tid < 128) nid_s[tid] = n_id[m0 + (tid < rows ? tid : rows - 1)];
    __syncthreads();

    const int warp = tid >> 5, lane = tid & 31;
    const int wm = warp & 3, wn = warp >> 2;
    const int lm = lane & 3, ln = lane >> 2;
    const int row0 = wm * 32 + lm * 8;
    const int col0 = wn * 64 + ln * 8;
    const int arow = tid >> 1, ac = (tid & 1) * 8;
    const int bk = tid >> 4, bn0 = (tid & 15) * 8;

    unsigned long long acc[8][4];
#pragma unroll
    for (int r = 0; r < 8; r++)
#pragma unroll
        for (int j = 0; j < 4; j++) acc[r][j] = 0ull;

    const int nid_a = nid_s[arow];
    for (int kc = 0; kc < 256; kc += 16) {
        // A tile: gathered x = [memory || node_feat], stored k-major transposed
        {
            int c = kc + ac;
            const float* srcrow = (c < 128) ? &memv[(size_t)nid_a * 128 + c]
                                            : &feat[(size_t)nid_a * 128 + (c - 128)];
            float4 v0 = *(const float4*)srcrow;
            float4 v1 = *(const float4*)(srcrow + 4);
            As[ac + 0][arow] = v0.x; As[ac + 1][arow] = v0.y;
            As[ac + 2][arow] = v0.z; As[ac + 3][arow] = v0.w;
            As[ac + 4][arow] = v1.x; As[ac + 5][arow] = v1.y;
            As[ac + 6][arow] = v1.z; As[ac + 7][arow] = v1.w;
        }
        // B tile
        {
            const float4* s4 = (const float4*)&W[(size_t)(kc + bk) * 128 + bn0];
            *(float4*)&Bs[bk][bn0] = s4[0];
            *(float4*)&Bs[bk][bn0 + 4] = s4[1];
        }
        __syncthreads();
#pragma unroll
        for (int k = 0; k < 16; k++) {
            float4 a0 = *(const float4*)&As[k][row0];
            float4 a1 = *(const float4*)&As[k][row0 + 4];
            const unsigned long long* bp = (const unsigned long long*)&Bs[k][col0];
            unsigned long long b2[4] = { bp[0], bp[1], bp[2], bp[3] };
            unsigned long long a2[8] = { dupf(a0.x), dupf(a0.y), dupf(a0.z), dupf(a0.w),
                                         dupf(a1.x), dupf(a1.y), dupf(a1.z), dupf(a1.w) };
#pragma unroll
            for (int r = 0; r < 8; r++)
#pragma unroll
                for (int j = 0; j < 4; j++) ffma2(acc[r][j], a2[r], b2[j]);
        }
        __syncthreads();
    }

    float4 bb0 = *(const float4*)&bias[col0];
    float4 bb1 = *(const float4*)&bias[col0 + 4];
#pragma unroll
    for (int r = 0; r < 8; r++) {
        int rl = row0 + r;
        if (rl < rows) {
            float2 f0 = u2f(acc[r][0]), f1 = u2f(acc[r][1]);
            float2 f2 = u2f(acc[r][2]), f3 = u2f(acc[r][3]);
            float* dst = &g_y[(size_t)(m0 + rl) * 512 + which * 128 + col0];
            *(float4*)&dst[0] = make_float4(f0.x + bb0.x, f0.y + bb0.y, f1.x + bb0.z, f1.y + bb0.w);
            *(float4*)&dst[4] = make_float4(f2.x + bb1.x, f2.y + bb1.y, f3.x + bb1.z, f3.y + bb1.w);
        }
    }
}

__global__ __launch_bounds__(256, 2) void k_edge_gemm(const int* __restrict__ src_a,
                                                      const int* __restrict__ e_id,
                                                      const float* __restrict__ edge_t,
                                                      const float* __restrict__ eraw,
                                                      const float* __restrict__ w_t,
                                                      const float* __restrict__ b_t,
                                                      const float* __restrict__ We) {
    __shared__ float As[16][128];
    __shared__ float Bs[16][128];
    __shared__ float relt_s[128];
    __shared__ int eid_s[128];
    const int m0 = blockIdx.x * 128;
    const int tid = threadIdx.x;
    int rows = ME - m0; if (rows > 128) rows = 128;
    if (tid < 128) {
        int r = (tid < rows ? tid : rows - 1);
        int e = e_id[m0 + r];
        eid_s[tid] = e;
        relt_s[tid] = edge_t[e] - g_lu[src_a[m0 + r]];
    }
    __syncthreads();

    const int warp = tid >> 5, lane = tid & 31;
    const int wm = warp & 3, wn = warp >> 2;
    const int lm = lane & 3, ln = lane >> 2;
    const int row0 = wm * 32 + lm * 8;
    const int col0 = wn * 64 + ln * 8;
    const int arow = tid >> 1, ac = (tid & 1) * 8;
    const int bk = tid >> 4, bn0 = (tid & 15) * 8;

    unsigned long long acc[8][4];
#pragma unroll
    for (int r = 0; r < 8; r++)
#pragma unroll
        for (int j = 0; j < 4; j++) acc[r][j] = 0ull;

    const int eid_a = eid_s[arow];
    const float rt_a = relt_s[arow];
    for (int kc = 0; kc < 256; kc += 16) {
        // A tile: [cos(rel_t*w + b) || raw_msg]
        {
            int c = kc + ac;
            float av[8];
            if (c < 128) {
                float4 w0 = *(const float4*)&w_t[c];
                float4 w1 = *(const float4*)&w_t[c + 4];
                float4 bt0 = *(const float4*)&b_t[c];
                float4 bt1 = *(const float4*)&b_t[c + 4];
                av[0] = fast_cos(fmaf(rt_a, w0.x, bt0.x));
                av[1] = fast_cos(fmaf(rt_a, w0.y, bt0.y));
                av[2] = fast_cos(fmaf(rt_a, w0.z, bt0.z));
                av[3] = fast_cos(fmaf(rt_a, w0.w, bt0.w));
                av[4] = fast_cos(fmaf(rt_a, w1.x, bt1.x));
                av[5] = fast_cos(fmaf(rt_a, w1.y, bt1.y));
                av[6] = fast_cos(fmaf(rt_a, w1.z, bt1.z));
                av[7] = fast_cos(fmaf(rt_a, w1.w, bt1.w));
            } else {
                const float* srcrow = &eraw[(size_t)eid_a * 128 + (c - 128)];
                float4 v0 = *(const float4*)srcrow;
                float4 v1 = *(const float4*)(srcrow + 4);
                av[0] = v0.x; av[1] = v0.y; av[2] = v0.z; av[3] = v0.w;
                av[4] = v1.x; av[5] = v1.y; av[6] = v1.z; av[7] = v1.w;
            }
#pragma unroll
            for (int i = 0; i < 8; i++) As[ac + i][arow] = av[i];
        }
        {
            const float4* s4 = (const float4*)&We[(size_t)(kc + bk) * 128 + bn0];
            *(float4*)&Bs[bk][bn0] = s4[0];
            *(float4*)&Bs[bk][bn0 + 4] = s4[1];
        }
        __syncthreads();
#pragma unroll
        for (int k = 0; k < 16; k++) {
            float4 a0 = *(const float4*)&As[k][row0];
            float4 a1 = *(const float4*)&As[k][row0 + 4];
            const unsigned long long* bp = (const unsigned long long*)&Bs[k][col0];
            unsigned long long b2[4] = { bp[0], bp[1], bp[2], bp[3] };
            unsigned long long a2[8] = { dupf(a0.x), dupf(a0.y), dupf(a0.z), dupf(a0.w),
                                         dupf(a1.x), dupf(a1.y), dupf(a1.z), dupf(a1.w) };
#pragma unroll
            for (int r = 0; r < 8; r++)
#pragma unroll
                for (int j = 0; j < 4; j++) ffma2(acc[r][j], a2[r], b2[j]);
        }
        __syncthreads();
    }

#pragma unroll
    for (int r = 0; r < 8; r++) {
        int rl = row0 + r;
        if (rl < rows) {
            float2 f0 = u2f(acc[r][0]), f1 = u2f(acc[r][1]);
            float2 f2 = u2f(acc[r][2]), f3 = u2f(acc[r][3]);
            float* dst = &g_e[(size_t)(m0 + rl) * 128 + col0];
            *(float4*)&dst[0] = make_float4(f0.x, f0.y, f1.x, f1.y);
            *(float4*)&dst[4] = make_float4(f2.x, f2.y, f3.x, f3.y);
        }
    }
}

// ---------------- fused attention: alpha = exp(q.(k+e)/8); accumulate -------
__global__ __launch_bounds__(256) void k_attn(const int* __restrict__ src_a,
                                              const int* __restrict__ dst_a,
                                              float* __restrict__ out) {
    int gw = (blockIdx.x * 256 + threadIdx.x) >> 5;
    int lane = threadIdx.x & 31;
    if (gw >= ME) return;
    int s = src_a[gw], d = dst_a[gw];
    const float4* qy = (const float4*)&g_y[(size_t)d * 512];
    const float4* ky = (const float4*)&g_y[(size_t)s * 512 + 128];
    const float4* vy = (const float4*)&g_y[(size_t)s * 512 + 256];
    const float4* ep = (const float4*)&g_e[(size_t)gw * 128];
    float4 q4 = qy[lane], k4 = ky[lane], v4 = vy[lane], e4 = ep[lane];
    float4 ke = make_float4(k4.x + e4.x, k4.y + e4.y, k4.z + e4.z, k4.w + e4.w);
    float p = q4.x * ke.x + q4.y * ke.y + q4.z * ke.z + q4.w * ke.w;
    p += __shfl_xor_sync(0xffffffffu, p, 8);
    p += __shfl_xor_sync(0xffffffffu, p, 4);
    p += __shfl_xor_sync(0xffffffffu, p, 2);
    p += __shfl_xor_sync(0xffffffffu, p, 1);
    float alpha = __expf(p * 0.125f);   // 1/sqrt(64)
    if ((lane & 15) == 0) atomicAdd(&g_denom[d * 2 + (lane >> 4)], alpha);
    float4 o = make_float4(alpha * (v4.x + e4.x), alpha * (v4.y + e4.y),
                           alpha * (v4.z + e4.z), alpha * (v4.w + e4.w));
    float* dptr = &out[(size_t)d * 128 + lane * 4];
    asm volatile("red.global.add.v4.f32 [%0], {%1,%2,%3,%4};"
                 :: "l"(dptr), "f"(o.x), "f"(o.y), "f"(o.z), "f"(o.w) : "memory");
}

// ---------------- finalize: out = out/denom + skip --------------------------
__global__ void k_final(float* __restrict__ out) {
    int i = blockIdx.x * 256 + threadIdx.x;   // one float4 per thread
    if (i >= KN * 32) return;
    int node = i >> 5;
    int j4 = (i & 31) * 4;
    int h = j4 >> 6;
    float den = g_denom[node * 2 + h];
    float inv = den > 0.f ? 1.f / den : 0.f;
    float4 u = *(float4*)&out[(size_t)node * 128 + j4];
    float4 sk = *(const float4*)&g_y[(size_t)node * 512 + 384 + j4];
    u.x = u.x * inv + sk.x;
    u.y = u.y * inv + sk.y;
    u.z = u.z * inv + sk.z;
    u.w = u.w * inv + sk.w;
    *(float4*)&out[(size_t)node * 128 + j4] = u;
}

// ---------------- launch -----------------------------------------------------
extern "C" void kernel_launch(void* const* d_in, const int* in_sizes, int n_in,
                              void* d_out, int out_size) {
    (void)in_sizes; (void)n_in; (void)out_size;
    const int*   n_id    = (const int*)d_in[0];
    const int*   eib     = (const int*)d_in[1];   // [2, M]: src then dst
    const int*   e_id    = (const int*)d_in[2];
    const float* nfeat   = (const float*)d_in[4];
    const float* eraw    = (const float*)d_in[5];
    const float* edge_t  = (const float*)d_in[6];
    const float* memv    = (const float*)d_in[7];
    const float* last_up = (const float*)d_in[8];
    const float* w_t     = (const float*)d_in[9];
    const float* b_t     = (const float*)d_in[10];
    NodeW p;
    p.W[0] = (const float*)d_in[11]; p.b[0] = (const float*)d_in[12];  // q
    p.W[1] = (const float*)d_in[13]; p.b[1] = (const float*)d_in[14];  // k
    p.W[2] = (const float*)d_in[15]; p.b[2] = (const float*)d_in[16];  // v
    const float* We = (const float*)d_in[17];
    p.W[3] = (const float*)d_in[18]; p.b[3] = (const float*)d_in[19];  // skip
    float* out = (float*)d_out;

    k_init<<<(KN * 128 + 255) / 256, 256>>>(out, last_up, n_id);
    dim3 gn(4, (KN + 127) / 128);
    k_node_gemm<<<gn, 256>>>(n_id, memv, nfeat, p);
    k_edge_gemm<<<(ME + 127) / 128, 256>>>(eib, e_id, edge_t, eraw, w_t, b_t, We);
    k_attn<<<ME / 8, 256>>>(eib, eib + ME, out);
    k_final<<<(KN * 32 + 255) / 256, 256>>>(out);
}

// round 3
// speedup vs baseline: 2.4190x; 1.3971x over previous
#include <cuda_runtime.h>
#include <cstdint>

#define KN 100000   // batch nodes
#define ME 600000   // edges

// ---------------- scratch (device globals: no allocations allowed) ----------
__device__ float g_y[(size_t)KN * 512];   // per node: [q(128) | k(128) | v(128) | skip(128)]
__device__ float g_e[(size_t)ME * 128];   // per edge: e = edge_attr @ We
__device__ float g_lu[KN];                // last_update gathered by n_id
__device__ float g_denom[KN * 2];         // softmax denominator per (node, head)

// ---------------- helpers ---------------------------------------------------
__device__ __forceinline__ float fast_cos(float x) {
    float n = rintf(x * 0.15915494309189535f);
    float r = fmaf(n, -6.28125f, x);
    r = fmaf(n, -1.9353071795864769e-3f, r);
    return __cosf(r);
}
__device__ __forceinline__ unsigned f2tf32(float v) {
    unsigned t;
    asm("cvt.rna.tf32.f32 %0, %1;" : "=r"(t) : "f"(v));
    return t;
}
__device__ __forceinline__ void mma_tf32(float* c, const unsigned* a, const unsigned* b) {
    asm volatile("mma.sync.aligned.m16n8k8.row.col.f32.tf32.tf32.f32 "
                 "{%0,%1,%2,%3}, {%4,%5,%6,%7}, {%8,%9}, {%0,%1,%2,%3};"
                 : "+f"(c[0]), "+f"(c[1]), "+f"(c[2]), "+f"(c[3])
                 : "r"(a[0]), "r"(a[1]), "r"(a[2]), "r"(a[3]), "r"(b[0]), "r"(b[1]));
}

// GEMM tiling constants (both GEMMs): BM=128, BN=128, BK=16, 256 threads.
// Warps 2(m) x 4(n); warp tile 64x32; per-warp 4x4 mma(16x8) per k8.
#define AST 20   // A smem stride (floats): conflict-free fragment reads
#define BST 20   // B smem stride

// ---------------- init: zero out/denom, gather last_update ------------------
__global__ void k_init(float* __restrict__ out,
                       const float* __restrict__ last_update,
                       const int* __restrict__ n_id) {
    int i = blockIdx.x * 256 + threadIdx.x;
    if (i < KN * 128) out[i] = 0.f;
    if (i < KN * 2) g_denom[i] = 0.f;
    if (i < KN) g_lu[i] = last_update[n_id[i]];
}

// ---------------- node GEMM (tf32 mma): y[:,w*128:+128] = x @ W + b ---------
struct NodeW { const float* W[4]; const float* b[4]; };

__global__ __launch_bounds__(256, 2) void k_node_gemm(const int* __restrict__ n_id,
                                                      const float* __restrict__ memv,
                                                      const float* __restrict__ feat,
                                                      NodeW p) {
    __shared__ unsigned As[128 * AST];
    __shared__ unsigned Bs[128 * BST];
    __shared__ int nid_s[128];
    const int which = blockIdx.x;
    const float* __restrict__ W = p.W[which];
    const float* __restrict__ bias = p.b[which];
    const int m0 = blockIdx.y * 128;
    const int tid = threadIdx.x;
    int rows = KN - m0; if (rows > 128) rows = 128;
    if (tid < 128) nid_s[tid] = n_id[m0 + (tid < rows ? tid : rows - 1)];
    __syncthreads();

    const int warp = tid >> 5, lane = tid & 31;
    const int wm = warp & 1, wn = warp >> 1;
    const int row_base = wm * 64, col_base = wn * 32;
    const int lr = lane >> 2, lc = lane & 3;
    const int arow = tid >> 1, ac = (tid & 1) * 8;   // A build
    const int bn = tid & 127, bkh = tid >> 7;        // B build

    float c[4][4][4];
#pragma unroll
    for (int mt = 0; mt < 4; mt++)
#pragma unroll
        for (int nt = 0; nt < 4; nt++)
#pragma unroll
            for (int i = 0; i < 4; i++) c[mt][nt][i] = 0.f;

    const int nid_a = nid_s[arow];
    for (int kc = 0; kc < 256; kc += 16) {
        // A tile [m][k], tf32-converted at store
        {
            int col = kc + ac;
            const float* srcrow = (col < 128) ? &memv[(size_t)nid_a * 128 + col]
                                              : &feat[(size_t)nid_a * 128 + (col - 128)];
            float4 v0 = *(const float4*)srcrow;
            float4 v1 = *(const float4*)(srcrow + 4);
            unsigned* d = &As[arow * AST + ac];
            d[0] = f2tf32(v0.x); d[1] = f2tf32(v0.y); d[2] = f2tf32(v0.z); d[3] = f2tf32(v0.w);
            d[4] = f2tf32(v1.x); d[5] = f2tf32(v1.y); d[6] = f2tf32(v1.z); d[7] = f2tf32(v1.w);
        }
        // B tile [n][k]
        {
#pragma unroll
            for (int i = 0; i < 8; i++)
                Bs[bn * BST + bkh * 8 + i] = f2tf32(W[(size_t)(kc + bkh * 8 + i) * 128 + bn]);
        }
        __syncthreads();
#pragma unroll
        for (int kh = 0; kh < 2; kh++) {
            int k0 = kh * 8;
            unsigned b[4][2], a[4][4];
#pragma unroll
            for (int nt = 0; nt < 4; nt++) {
                int n = col_base + nt * 8 + lr;
                b[nt][0] = Bs[n * BST + k0 + lc];
                b[nt][1] = Bs[n * BST + k0 + 4 + lc];
            }
#pragma unroll
            for (int mt = 0; mt < 4; mt++) {
                int r = row_base + mt * 16 + lr;
                a[mt][0] = As[r * AST + k0 + lc];
                a[mt][1] = As[(r + 8) * AST + k0 + lc];
                a[mt][2] = As[r * AST + k0 + 4 + lc];
                a[mt][3] = As[(r + 8) * AST + k0 + 4 + lc];
            }
#pragma unroll
            for (int mt = 0; mt < 4; mt++)
#pragma unroll
                for (int nt = 0; nt < 4; nt++) mma_tf32(c[mt][nt], a[mt], b[nt]);
        }
        __syncthreads();
    }

#pragma unroll
    for (int nt = 0; nt < 4; nt++) {
        int col = col_base + nt * 8 + lc * 2;
        float2 bb = *(const float2*)&bias[col];
#pragma unroll
        for (int mt = 0; mt < 4; mt++) {
            int r0 = row_base + mt * 16 + lr;
            if (r0 < rows) {
                float* dst = &g_y[(size_t)(m0 + r0) * 512 + which * 128 + col];
                *(float2*)dst = make_float2(c[mt][nt][0] + bb.x, c[mt][nt][1] + bb.y);
            }
            if (r0 + 8 < rows) {
                float* dst = &g_y[(size_t)(m0 + r0 + 8) * 512 + which * 128 + col];
                *(float2*)dst = make_float2(c[mt][nt][2] + bb.x, c[mt][nt][3] + bb.y);
            }
        }
    }
}

// ---------------- edge GEMM (tf32 mma): e = [cos(rel_t*w+b) || msg] @ We ----
__global__ __launch_bounds__(256, 2) void k_edge_gemm(const int* __restrict__ src_a,
                                                      const int* __restrict__ e_id,
                                                      const float* __restrict__ edge_t,
                                                      const float* __restrict__ eraw,
                                                      const float* __restrict__ w_t,
                                                      const float* __restrict__ b_t,
                                                      const float* __restrict__ We) {
    __shared__ unsigned As[128 * AST];
    __shared__ unsigned Bs[128 * BST];
    __shared__ float relt_s[128];
    __shared__ int eid_s[128];
    const int m0 = blockIdx.x * 128;
    const int tid = threadIdx.x;
    int rows = ME - m0; if (rows > 128) rows = 128;
    if (tid < 128) {
        int r = (tid < rows ? tid : rows - 1);
        int e = e_id[m0 + r];
        eid_s[tid] = e;
        relt_s[tid] = edge_t[e] - g_lu[src_a[m0 + r]];
    }
    __syncthreads();

    const int warp = tid >> 5, lane = tid & 31;
    const int wm = warp & 1, wn = warp >> 1;
    const int row_base = wm * 64, col_base = wn * 32;
    const int lr = lane >> 2, lc = lane & 3;
    const int arow = tid >> 1, ac = (tid & 1) * 8;
    const int bn = tid & 127, bkh = tid >> 7;

    float c[4][4][4];
#pragma unroll
    for (int mt = 0; mt < 4; mt++)
#pragma unroll
        for (int nt = 0; nt < 4; nt++)
#pragma unroll
            for (int i = 0; i < 4; i++) c[mt][nt][i] = 0.f;

    const int eid_a = eid_s[arow];
    const float rt_a = relt_s[arow];
    for (int kc = 0; kc < 256; kc += 16) {
        // A tile: [cos(rel_t*w + b) || raw_msg], tf32 at store
        {
            int col = kc + ac;
            float av[8];
            if (col < 128) {
                float4 w0 = *(const float4*)&w_t[col];
                float4 w1 = *(const float4*)&w_t[col + 4];
                float4 bt0 = *(const float4*)&b_t[col];
                float4 bt1 = *(const float4*)&b_t[col + 4];
                av[0] = fast_cos(fmaf(rt_a, w0.x, bt0.x));
                av[1] = fast_cos(fmaf(rt_a, w0.y, bt0.y));
                av[2] = fast_cos(fmaf(rt_a, w0.z, bt0.z));
                av[3] = fast_cos(fmaf(rt_a, w0.w, bt0.w));
                av[4] = fast_cos(fmaf(rt_a, w1.x, bt1.x));
                av[5] = fast_cos(fmaf(rt_a, w1.y, bt1.y));
                av[6] = fast_cos(fmaf(rt_a, w1.z, bt1.z));
                av[7] = fast_cos(fmaf(rt_a, w1.w, bt1.w));
            } else {
                const float* srcrow = &eraw[(size_t)eid_a * 128 + (col - 128)];
                float4 v0 = *(const float4*)srcrow;
                float4 v1 = *(const float4*)(srcrow + 4);
                av[0] = v0.x; av[1] = v0.y; av[2] = v0.z; av[3] = v0.w;
                av[4] = v1.x; av[5] = v1.y; av[6] = v1.z; av[7] = v1.w;
            }
            unsigned* d = &As[arow * AST + ac];
#pragma unroll
            for (int i = 0; i < 8; i++) d[i] = f2tf32(av[i]);
        }
        {
#pragma unroll
            for (int i = 0; i < 8; i++)
                Bs[bn * BST + bkh * 8 + i] = f2tf32(We[(size_t)(kc + bkh * 8 + i) * 128 + bn]);
        }
        __syncthreads();
#pragma unroll
        for (int kh = 0; kh < 2; kh++) {
            int k0 = kh * 8;
            unsigned b[4][2], a[4][4];
#pragma unroll
            for (int nt = 0; nt < 4; nt++) {
                int n = col_base + nt * 8 + lr;
                b[nt][0] = Bs[n * BST + k0 + lc];
                b[nt][1] = Bs[n * BST + k0 + 4 + lc];
            }
#pragma unroll
            for (int mt = 0; mt < 4; mt++) {
                int r = row_base + mt * 16 + lr;
                a[mt][0] = As[r * AST + k0 + lc];
                a[mt][1] = As[(r + 8) * AST + k0 + lc];
                a[mt][2] = As[r * AST + k0 + 4 + lc];
                a[mt][3] = As[(r + 8) * AST + k0 + 4 + lc];
            }
#pragma unroll
            for (int mt = 0; mt < 4; mt++)
#pragma unroll
                for (int nt = 0; nt < 4; nt++) mma_tf32(c[mt][nt], a[mt], b[nt]);
        }
        __syncthreads();
    }

#pragma unroll
    for (int nt = 0; nt < 4; nt++) {
        int col = col_base + nt * 8 + lc * 2;
#pragma unroll
        for (int mt = 0; mt < 4; mt++) {
            int r0 = row_base + mt * 16 + lr;
            if (r0 < rows)
                *(float2*)&g_e[(size_t)(m0 + r0) * 128 + col] =
                    make_float2(c[mt][nt][0], c[mt][nt][1]);
            if (r0 + 8 < rows)
                *(float2*)&g_e[(size_t)(m0 + r0 + 8) * 128 + col] =
                    make_float2(c[mt][nt][2], c[mt][nt][3]);
        }
    }
}

// ---------------- fused attention: alpha = exp(q.(k+e)/8); accumulate -------
__global__ __launch_bounds__(256) void k_attn(const int* __restrict__ src_a,
                                              const int* __restrict__ dst_a,
                                              float* __restrict__ out) {
    int gw = (blockIdx.x * 256 + threadIdx.x) >> 5;
    int lane = threadIdx.x & 31;
    if (gw >= ME) return;
    int s = src_a[gw], d = dst_a[gw];
    const float4* qy = (const float4*)&g_y[(size_t)d * 512];
    const float4* ky = (const float4*)&g_y[(size_t)s * 512 + 128];
    const float4* vy = (const float4*)&g_y[(size_t)s * 512 + 256];
    const float4* ep = (const float4*)&g_e[(size_t)gw * 128];
    float4 q4 = qy[lane], k4 = ky[lane], v4 = vy[lane], e4 = ep[lane];
    float4 ke = make_float4(k4.x + e4.x, k4.y + e4.y, k4.z + e4.z, k4.w + e4.w);
    float p = q4.x * ke.x + q4.y * ke.y + q4.z * ke.z + q4.w * ke.w;
    p += __shfl_xor_sync(0xffffffffu, p, 8);
    p += __shfl_xor_sync(0xffffffffu, p, 4);
    p += __shfl_xor_sync(0xffffffffu, p, 2);
    p += __shfl_xor_sync(0xffffffffu, p, 1);
    float alpha = __expf(p * 0.125f);   // 1/sqrt(64)
    if ((lane & 15) == 0) atomicAdd(&g_denom[d * 2 + (lane >> 4)], alpha);
    float4 o = make_float4(alpha * (v4.x + e4.x), alpha * (v4.y + e4.y),
                           alpha * (v4.z + e4.z), alpha * (v4.w + e4.w));
    float* dptr = &out[(size_t)d * 128 + lane * 4];
    asm volatile("red.global.add.v4.f32 [%0], {%1,%2,%3,%4};"
                 :: "l"(dptr), "f"(o.x), "f"(o.y), "f"(o.z), "f"(o.w) : "memory");
}

// ---------------- finalize: out = out/denom + skip --------------------------
__global__ void k_final(float* __restrict__ out) {
    int i = blockIdx.x * 256 + threadIdx.x;
    if (i >= KN * 32) return;
    int node = i >> 5;
    int j4 = (i & 31) * 4;
    int h = j4 >> 6;
    float den = g_denom[node * 2 + h];
    float inv = den > 0.f ? 1.f / den : 0.f;
    float4 u = *(float4*)&out[(size_t)node * 128 + j4];
    float4 sk = *(const float4*)&g_y[(size_t)node * 512 + 384 + j4];
    u.x = u.x * inv + sk.x;
    u.y = u.y * inv + sk.y;
    u.z = u.z * inv + sk.z;
    u.w = u.w * inv + sk.w;
    *(float4*)&out[(size_t)node * 128 + j4] = u;
}

// ---------------- launch -----------------------------------------------------
extern "C" void kernel_launch(void* const* d_in, const int* in_sizes, int n_in,
                              void* d_out, int out_size) {
    (void)in_sizes; (void)n_in; (void)out_size;
    const int*   n_id    = (const int*)d_in[0];
    const int*   eib     = (const int*)d_in[1];   // [2, M]: src then dst
    const int*   e_id    = (const int*)d_in[2];
    const float* nfeat   = (const float*)d_in[4];
    const float* eraw    = (const float*)d_in[5];
    const float* edge_t  = (const float*)d_in[6];
    const float* memv    = (const float*)d_in[7];
    const float* last_up = (const float*)d_in[8];
    const float* w_t     = (const float*)d_in[9];
    const float* b_t     = (const float*)d_in[10];
    NodeW p;
    p.W[0] = (const float*)d_in[11]; p.b[0] = (const float*)d_in[12];  // q
    p.W[1] = (const float*)d_in[13]; p.b[1] = (const float*)d_in[14];  // k
    p.W[2] = (const float*)d_in[15]; p.b[2] = (const float*)d_in[16];  // v
    const float* We = (const float*)d_in[17];
    p.W[3] = (const float*)d_in[18]; p.b[3] = (const float*)d_in[19];  // skip
    float* out = (float*)d_out;

    k_init<<<(KN * 128 + 255) / 256, 256>>>(out, last_up, n_id);
    dim3 gn(4, (KN + 127) / 128);
    k_node_gemm<<<gn, 256>>>(n_id, memv, nfeat, p);
    k_edge_gemm<<<(ME + 127) / 128, 256>>>(eib, e_id, edge_t, eraw, w_t, b_t, We);
    k_attn<<<ME / 8, 256>>>(eib, eib + ME, out);
    k_final<<<(KN * 32 + 255) / 256, 256>>>(out);
}

// round 5
// speedup vs baseline: 3.2483x; 1.3428x over previous
#include <cuda_runtime.h>
#include <cstdint>

#define KN 100000   // batch nodes
#define ME 600000   // edges

// ---------------- scratch (device globals: no allocations allowed) ----------
__device__ float g_y[(size_t)KN * 512];   // per node: [q(128) | k(128) | v(128) | skip(128)]
__device__ float g_e[(size_t)ME * 128];   // per edge: e = edge_attr @ We
__device__ float g_lu[KN];                // last_update gathered by n_id
__device__ float g_denom[KN * 2];         // softmax denominator per (node, head)

// ---------------- helpers ---------------------------------------------------
__device__ __forceinline__ float fast_cos(float x) {
    float n = rintf(x * 0.15915494309189535f);
    float r = fmaf(n, -6.28125f, x);
    r = fmaf(n, -1.9353071795864769e-3f, r);
    return __cosf(r);
}
__device__ __forceinline__ unsigned f2tf32(float v) {
    unsigned t;
    asm("cvt.rna.tf32.f32 %0, %1;" : "=r"(t) : "f"(v));
    return t;
}
__device__ __forceinline__ void mma_tf32(float* c, const unsigned* a, const unsigned* b) {
    asm volatile("mma.sync.aligned.m16n8k8.row.col.f32.tf32.tf32.f32 "
                 "{%0,%1,%2,%3}, {%4,%5,%6,%7}, {%8,%9}, {%0,%1,%2,%3};"
                 : "+f"(c[0]), "+f"(c[1]), "+f"(c[2]), "+f"(c[3])
                 : "r"(a[0]), "r"(a[1]), "r"(a[2]), "r"(a[3]), "r"(b[0]), "r"(b[1]));
}

// GEMM tiling: BM=128, BN=128, BK=16, 256 threads, warps 2(m) x 4(n),
// warp tile 64x32, double-buffered smem + register prefetch pipeline.
#define AST 20   // smem stride (u32): conflict-free fragment reads
#define BUFSZ (128 * AST)

// ---------------- init -------------------------------------------------------
__global__ void k_init(float* __restrict__ out,
                       const float* __restrict__ last_update,
                       const int* __restrict__ n_id) {
    int i = blockIdx.x * 256 + threadIdx.x;
    if (i < KN * 128) out[i] = 0.f;
    if (i < KN * 2) g_denom[i] = 0.f;
    if (i < KN) g_lu[i] = last_update[n_id[i]];
}

// ---------------- shared mainloop compute (both GEMMs) ----------------------
__device__ __forceinline__ void gemm_compute(const unsigned* __restrict__ As,
                                             const unsigned* __restrict__ Bs,
                                             int row_base, int col_base,
                                             int lr, int lc, float c[4][4][4]) {
#pragma unroll
    for (int kh = 0; kh < 2; kh++) {
        int k0 = kh * 8;
        unsigned b[4][2], a[4][4];
#pragma unroll
        for (int nt = 0; nt < 4; nt++) {
            int n = col_base + nt * 8 + lr;
            b[nt][0] = Bs[n * AST + k0 + lc];
            b[nt][1] = Bs[n * AST + k0 + 4 + lc];
        }
#pragma unroll
        for (int mt = 0; mt < 4; mt++) {
            int r = row_base + mt * 16 + lr;
            a[mt][0] = As[r * AST + k0 + lc];
            a[mt][1] = As[(r + 8) * AST + k0 + lc];
            a[mt][2] = As[r * AST + k0 + 4 + lc];
            a[mt][3] = As[(r + 8) * AST + k0 + 4 + lc];
        }
#pragma unroll
        for (int mt = 0; mt < 4; mt++)
#pragma unroll
            for (int nt = 0; nt < 4; nt++) mma_tf32(c[mt][nt], a[mt], b[nt]);
    }
}

// ---------------- node GEMM (pipelined tf32 mma) -----------------------------
struct NodeW { const float* W[4]; const float* b[4]; };

__global__ __launch_bounds__(256, 2) void k_node_gemm(const int* __restrict__ n_id,
                                                      const float* __restrict__ memv,
                                                      const float* __restrict__ feat,
                                                      NodeW p) {
    __shared__ unsigned As[2][BUFSZ];
    __shared__ unsigned Bs[2][BUFSZ];
    __shared__ int nid_s[128];
    const int which = blockIdx.x;
    const float* __restrict__ W = p.W[which];
    const float* __restrict__ bias = p.b[which];
    const int m0 = blockIdx.y * 128;
    const int tid = threadIdx.x;
    int rows = KN - m0; if (rows > 128) rows = 128;
    if (tid < 128) nid_s[tid] = n_id[m0 + (tid < rows ? tid : rows - 1)];
    __syncthreads();

    const int warp = tid >> 5, lane = tid & 31;
    const int wm = warp & 1, wn = warp >> 1;
    const int row_base = wm * 64, col_base = wn * 32;
    const int lr = lane >> 2, lc = lane & 3;
    const int arow = tid >> 1, ac = (tid & 1) * 8;   // A build
    const int bn = tid & 127, bkh = tid >> 7;        // B build

    float c[4][4][4];
#pragma unroll
    for (int mt = 0; mt < 4; mt++)
#pragma unroll
        for (int nt = 0; nt < 4; nt++)
#pragma unroll
            for (int i = 0; i < 4; i++) c[mt][nt][i] = 0.f;

    const int nid_a = nid_s[arow];
    const float* arow_mem = &memv[(size_t)nid_a * 128];
    const float* arow_feat = &feat[(size_t)nid_a * 128];

    float apre[8], bpre[8];
    // loaders ---------------------------------------------------------------
    auto load_a = [&](int ch, float* ap) {
        int col = ch * 16 + ac;
        const float* srcrow = (col < 128) ? (arow_mem + col) : (arow_feat + col - 128);
        float4 v0 = *(const float4*)srcrow;
        float4 v1 = *(const float4*)(srcrow + 4);
        ap[0] = v0.x; ap[1] = v0.y; ap[2] = v0.z; ap[3] = v0.w;
        ap[4] = v1.x; ap[5] = v1.y; ap[6] = v1.z; ap[7] = v1.w;
    };
    auto load_b = [&](int ch, float* bp) {
        int k0 = ch * 16 + bkh * 8;
#pragma unroll
        for (int i = 0; i < 8; i++) bp[i] = W[(size_t)(k0 + i) * 128 + bn];
    };
    auto store_ab = [&](int buf, const float* ap, const float* bp) {
        unsigned* da = &As[buf][arow * AST + ac];
#pragma unroll
        for (int i = 0; i < 8; i++) da[i] = f2tf32(ap[i]);
        unsigned* db = &Bs[buf][bn * AST + bkh * 8];
#pragma unroll
        for (int i = 0; i < 8; i++) db[i] = f2tf32(bp[i]);
    };

    load_a(0, apre); load_b(0, bpre);
    store_ab(0, apre, bpre);
    __syncthreads();

    for (int ch = 0; ch < 16; ch++) {
        int buf = ch & 1;
        if (ch < 15) { load_a(ch + 1, apre); load_b(ch + 1, bpre); }
        gemm_compute(As[buf], Bs[buf], row_base, col_base, lr, lc, c);
        if (ch < 15) {
            store_ab(buf ^ 1, apre, bpre);
            __syncthreads();
        }
    }

#pragma unroll
    for (int nt = 0; nt < 4; nt++) {
        int col = col_base + nt * 8 + lc * 2;
        float2 bb = *(const float2*)&bias[col];
#pragma unroll
        for (int mt = 0; mt < 4; mt++) {
            int r0 = row_base + mt * 16 + lr;
            if (r0 < rows) {
                float* dst = &g_y[(size_t)(m0 + r0) * 512 + which * 128 + col];
                *(float2*)dst = make_float2(c[mt][nt][0] + bb.x, c[mt][nt][1] + bb.y);
            }
            if (r0 + 8 < rows) {
                float* dst = &g_y[(size_t)(m0 + r0 + 8) * 512 + which * 128 + col];
                *(float2*)dst = make_float2(c[mt][nt][2] + bb.x, c[mt][nt][3] + bb.y);
            }
        }
    }
}

// ---------------- edge GEMM (pipelined tf32 mma) -----------------------------
__global__ __launch_bounds__(256, 2) void k_edge_gemm(const int* __restrict__ src_a,
                                                      const int* __restrict__ e_id,
                                                      const float* __restrict__ edge_t,
                                                      const float* __restrict__ eraw,
                                                      const float* __restrict__ w_t,
                                                      const float* __restrict__ b_t,
                                                      const float* __restrict__ We) {
    __shared__ unsigned As[2][BUFSZ];
    __shared__ unsigned Bs[2][BUFSZ];
    __shared__ float relt_s[128];
    __shared__ int eid_s[128];
    const int m0 = blockIdx.x * 128;
    const int tid = threadIdx.x;
    int rows = ME - m0; if (rows > 128) rows = 128;
    if (tid < 128) {
        int r = (tid < rows ? tid : rows - 1);
        int e = e_id[m0 + r];
        eid_s[tid] = e;
        relt_s[tid] = edge_t[e] - g_lu[src_a[m0 + r]];
    }
    __syncthreads();

    const int warp = tid >> 5, lane = tid & 31;
    const int wm = warp & 1, wn = warp >> 1;
    const int row_base = wm * 64, col_base = wn * 32;
    const int lr = lane >> 2, lc = lane & 3;
    const int arow = tid >> 1, ac = (tid & 1) * 8;
    const int bn = tid & 127, bkh = tid >> 7;

    float c[4][4][4];
#pragma unroll
    for (int mt = 0; mt < 4; mt++)
#pragma unroll
        for (int nt = 0; nt < 4; nt++)
#pragma unroll
            for (int i = 0; i < 4; i++) c[mt][nt][i] = 0.f;

    const float rt_a = relt_s[arow];
    const float* arow_msg = &eraw[(size_t)eid_s[arow] * 128];

    float apre[8], bpre[8];
    auto load_a = [&](int ch, float* ap) {
        int col = ch * 16 + ac;
        if (col < 128) {
            float4 w0 = *(const float4*)&w_t[col];
            float4 w1 = *(const float4*)&w_t[col + 4];
            float4 bt0 = *(const float4*)&b_t[col];
            float4 bt1 = *(const float4*)&b_t[col + 4];
            ap[0] = fast_cos(fmaf(rt_a, w0.x, bt0.x));
            ap[1] = fast_cos(fmaf(rt_a, w0.y, bt0.y));
            ap[2] = fast_cos(fmaf(rt_a, w0.z, bt0.z));
            ap[3] = fast_cos(fmaf(rt_a, w0.w, bt0.w));
            ap[4] = fast_cos(fmaf(rt_a, w1.x, bt1.x));
            ap[5] = fast_cos(fmaf(rt_a, w1.y, bt1.y));
            ap[6] = fast_cos(fmaf(rt_a, w1.z, bt1.z));
            ap[7] = fast_cos(fmaf(rt_a, w1.w, bt1.w));
        } else {
            const float* srcrow = arow_msg + (col - 128);
            float4 v0 = *(const float4*)srcrow;
            float4 v1 = *(const float4*)(srcrow + 4);
            ap[0] = v0.x; ap[1] = v0.y; ap[2] = v0.z; ap[3] = v0.w;
            ap[4] = v1.x; ap[5] = v1.y; ap[6] = v1.z; ap[7] = v1.w;
        }
    };
    auto load_b = [&](int ch, float* bp) {
        int k0 = ch * 16 + bkh * 8;
#pragma unroll
        for (int i = 0; i < 8; i++) bp[i] = We[(size_t)(k0 + i) * 128 + bn];
    };
    auto store_ab = [&](int buf, const float* ap, const float* bp) {
        unsigned* da = &As[buf][arow * AST + ac];
#pragma unroll
        for (int i = 0; i < 8; i++) da[i] = f2tf32(ap[i]);
        unsigned* db = &Bs[buf][bn * AST + bkh * 8];
#pragma unroll
        for (int i = 0; i < 8; i++) db[i] = f2tf32(bp[i]);
    };

    load_a(0, apre); load_b(0, bpre);
    store_ab(0, apre, bpre);
    __syncthreads();

    for (int ch = 0; ch < 16; ch++) {
        int buf = ch & 1;
        if (ch < 15) { load_a(ch + 1, apre); load_b(ch + 1, bpre); }
        gemm_compute(As[buf], Bs[buf], row_base, col_base, lr, lc, c);
        if (ch < 15) {
            store_ab(buf ^ 1, apre, bpre);
            __syncthreads();
        }
    }

#pragma unroll
    for (int nt = 0; nt < 4; nt++) {
        int col = col_base + nt * 8 + lc * 2;
#pragma unroll
        for (int mt = 0; mt < 4; mt++) {
            int r0 = row_base + mt * 16 + lr;
            if (r0 < rows)
                *(float2*)&g_e[(size_t)(m0 + r0) * 128 + col] =
                    make_float2(c[mt][nt][0], c[mt][nt][1]);
            if (r0 + 8 < rows)
                *(float2*)&g_e[(size_t)(m0 + r0 + 8) * 128 + col] =
                    make_float2(c[mt][nt][2], c[mt][nt][3]);
        }
    }
}

// ---------------- fused attention: alpha = exp(q.(k+e)/8); accumulate -------
__global__ __launch_bounds__(256) void k_attn(const int* __restrict__ src_a,
                                              const int* __restrict__ dst_a,
                                              float* __restrict__ out) {
    int gw = (blockIdx.x * 256 + threadIdx.x) >> 5;
    int lane = threadIdx.x & 31;
    if (gw >= ME) return;
    int s = src_a[gw], d = dst_a[gw];
    const float4* qy = (const float4*)&g_y[(size_t)d * 512];
    const float4* ky = (const float4*)&g_y[(size_t)s * 512 + 128];
    const float4* vy = (const float4*)&g_y[(size_t)s * 512 + 256];
    const float4* ep = (const float4*)&g_e[(size_t)gw * 128];
    float4 q4 = qy[lane], k4 = ky[lane], v4 = vy[lane], e4 = ep[lane];
    float4 ke = make_float4(k4.x + e4.x, k4.y + e4.y, k4.z + e4.z, k4.w + e4.w);
    float p = q4.x * ke.x + q4.y * ke.y + q4.z * ke.z + q4.w * ke.w;
    p += __shfl_xor_sync(0xffffffffu, p, 8);
    p += __shfl_xor_sync(0xffffffffu, p, 4);
    p += __shfl_xor_sync(0xffffffffu, p, 2);
    p += __shfl_xor_sync(0xffffffffu, p, 1);
    float alpha = __expf(p * 0.125f);   // 1/sqrt(64)
    if ((lane & 15) == 0) atomicAdd(&g_denom[d * 2 + (lane >> 4)], alpha);
    float4 o = make_float4(alpha * (v4.x + e4.x), alpha * (v4.y + e4.y),
                           alpha * (v4.z + e4.z), alpha * (v4.w + e4.w));
    float* dptr = &out[(size_t)d * 128 + lane * 4];
    asm volatile("red.global.add.v4.f32 [%0], {%1,%2,%3,%4};"
                 :: "l"(dptr), "f"(o.x), "f"(o.y), "f"(o.z), "f"(o.w) : "memory");
}

// ---------------- finalize: out = out/denom + skip --------------------------
__global__ void k_final(float* __restrict__ out) {
    int i = blockIdx.x * 256 + threadIdx.x;
    if (i >= KN * 32) return;
    int node = i >> 5;
    int j4 = (i & 31) * 4;
    int h = j4 >> 6;
    float den = g_denom[node * 2 + h];
    float inv = den > 0.f ? 1.f / den : 0.f;
    float4 u = *(float4*)&out[(size_t)node * 128 + j4];
    float4 sk = *(const float4*)&g_y[(size_t)node * 512 + 384 + j4];
    u.x = u.x * inv + sk.x;
    u.y = u.y * inv + sk.y;
    u.z = u.z * inv + sk.z;
    u.w = u.w * inv + sk.w;
    *(float4*)&out[(size_t)node * 128 + j4] = u;
}

// ---------------- launch -----------------------------------------------------
extern "C" void kernel_launch(void* const* d_in, const int* in_sizes, int n_in,
                              void* d_out, int out_size) {
    (void)in_sizes; (void)n_in; (void)out_size;
    const int*   n_id    = (const int*)d_in[0];
    const int*   eib     = (const int*)d_in[1];   // [2, M]: src then dst
    const int*   e_id    = (const int*)d_in[2];
    const float* nfeat   = (const float*)d_in[4];
    const float* eraw    = (const float*)d_in[5];
    const float* edge_t  = (const float*)d_in[6];
    const float* memv    = (const float*)d_in[7];
    const float* last_up = (const float*)d_in[8];
    const float* w_t     = (const float*)d_in[9];
    const float* b_t     = (const float*)d_in[10];
    NodeW p;
    p.W[0] = (const float*)d_in[11]; p.b[0] = (const float*)d_in[12];  // q
    p.W[1] = (const float*)d_in[13]; p.b[1] = (const float*)d_in[14];  // k
    p.W[2] = (const float*)d_in[15]; p.b[2] = (const float*)d_in[16];  // v
    const float* We = (const float*)d_in[17];
    p.W[3] = (const float*)d_in[18]; p.b[3] = (const float*)d_in[19];  // skip
    float* out = (float*)d_out;

    k_init<<<(KN * 128 + 255) / 256, 256>>>(out, last_up, n_id);
    dim3 gn(4, (KN + 127) / 128);
    k_node_gemm<<<gn, 256>>>(n_id, memv, nfeat, p);
    k_edge_gemm<<<(ME + 127) / 128, 256>>>(eib, e_id, edge_t, eraw, w_t, b_t, We);
    k_attn<<<ME / 8, 256>>>(eib, eib + ME, out);
    k_final<<<(KN * 32 + 255) / 256, 256>>>(out);
}

// round 6
// speedup vs baseline: 3.6188x; 1.1141x over previous
#include <cuda_runtime.h>
#include <cuda_fp16.h>
#include <cstdint>

#define KN 100000   // batch nodes
#define ME 600000   // edges

// ---------------- scratch (device globals) ----------------------------------
__device__ __half g_yh[(size_t)KN * 512];   // per node: [q | k | v | skip] x128 (fp16)
__device__ __half g_eh[(size_t)ME * 128];   // per edge: e (fp16)
__device__ __half g_wT[(size_t)5 * 128 * 256]; // transposed fp16 weights [mat][n][k]
__device__ float g_lu[KN];
__device__ float g_denom[KN * 2];

// ---------------- helpers ---------------------------------------------------
__device__ __forceinline__ float fast_cos(float x) {
    float n = rintf(x * 0.15915494309189535f);
    float r = fmaf(n, -6.28125f, x);
    r = fmaf(n, -1.9353071795864769e-3f, r);
    return __cosf(r);
}
__device__ __forceinline__ void mma_f16(float* c, const unsigned* a, const unsigned* b) {
    asm volatile("mma.sync.aligned.m16n8k16.row.col.f32.f16.f16.f32 "
                 "{%0,%1,%2,%3}, {%4,%5,%6,%7}, {%8,%9}, {%0,%1,%2,%3};"
                 : "+f"(c[0]), "+f"(c[1]), "+f"(c[2]), "+f"(c[3])
                 : "r"(a[0]), "r"(a[1]), "r"(a[2]), "r"(a[3]), "r"(b[0]), "r"(b[1]));
}
__device__ __forceinline__ unsigned pkh2(float a, float b) {
    half2 h = __floats2half2_rn(a, b);
    return *(unsigned*)&h;
}
__device__ __forceinline__ float2 uph2(unsigned u) {
    return __half22float2(*(half2*)&u);
}

// ---------------- prep: transpose+convert weights to fp16 -------------------
__global__ void k_prep(const float* __restrict__ W0, const float* __restrict__ W1,
                       const float* __restrict__ W2, const float* __restrict__ W3,
                       const float* __restrict__ W4) {
    int i = blockIdx.x * 256 + threadIdx.x;
    if (i >= 5 * 32768) return;
    int mat = i >> 15, rem = i & 32767;
    int k = rem >> 7, n = rem & 127;
    const float* src = (mat == 0) ? W0 : (mat == 1) ? W1 : (mat == 2) ? W2 : (mat == 3) ? W3 : W4;
    g_wT[((size_t)mat * 128 + n) * 256 + k] = __float2half_rn(src[rem]);
}

// ---------------- init: zero out/denom, gather last_update ------------------
__global__ void k_init(float* __restrict__ out,
                       const float* __restrict__ last_update,
                       const int* __restrict__ n_id) {
    int i = blockIdx.x * 256 + threadIdx.x;
    if (i < KN * 128) out[i] = 0.f;
    if (i < KN * 2) g_denom[i] = 0.f;
    if (i < KN) g_lu[i] = last_update[n_id[i]];
}

// ============================================================================
// fp16 GEMM: BM=128, BN=128, BK=16, 256 threads, warps 2(m)x4(n), 64x32/warp.
// SMEM tiles stored as [kh(2)][row(128)][8 halves]; fragment LDS.32 conflict-free.
// ============================================================================
#define TBUF 2048   // halves per tile buffer (2*128*8)

__device__ __forceinline__ void gemm_compute16(const unsigned* __restrict__ As,
                                               const unsigned* __restrict__ Bs,
                                               int row_base, int col_base,
                                               int lr, int lc, float c[4][4][4]) {
    unsigned b[4][2], a[4][4];
#pragma unroll
    for (int nt = 0; nt < 4; nt++) {
        int n = col_base + nt * 8 + lr;
        b[nt][0] = Bs[n * 4 + lc];
        b[nt][1] = Bs[512 + n * 4 + lc];
    }
#pragma unroll
    for (int mt = 0; mt < 4; mt++) {
        int r = row_base + mt * 16 + lr;
        a[mt][0] = As[r * 4 + lc];
        a[mt][1] = As[(r + 8) * 4 + lc];
        a[mt][2] = As[512 + r * 4 + lc];
        a[mt][3] = As[512 + (r + 8) * 4 + lc];
    }
#pragma unroll
    for (int mt = 0; mt < 4; mt++)
#pragma unroll
        for (int nt = 0; nt < 4; nt++) mma_f16(c[mt][nt], a[mt], b[nt]);
}

// ---------------- node GEMM ---------------------------------------------------
struct NodeB { const float* b[4]; };

__global__ __launch_bounds__(256, 2) void k_node_gemm(const int* __restrict__ n_id,
                                                      const float* __restrict__ memv,
                                                      const float* __restrict__ feat,
                                                      NodeB pb) {
    __shared__ __half As[2][TBUF];
    __shared__ __half Bs[2][TBUF];
    __shared__ int nid_s[128];
    const int which = blockIdx.x;
    const __half* __restrict__ Wt = &g_wT[(size_t)which * 32768];
    const float* __restrict__ bias = pb.b[which];
    const int m0 = blockIdx.y * 128;
    const int tid = threadIdx.x;
    int rows = KN - m0; if (rows > 128) rows = 128;
    if (tid < 128) nid_s[tid] = n_id[m0 + (tid < rows ? tid : rows - 1)];
    __syncthreads();

    const int warp = tid >> 5, lane = tid & 31;
    const int wm = warp & 1, wn = warp >> 1;
    const int row_base = wm * 64, col_base = wn * 32;
    const int lr = lane >> 2, lc = lane & 3;
    const int trow = tid & 127, tkh = tid >> 7;   // tile-build mapping

    float c[4][4][4];
#pragma unroll
    for (int mt = 0; mt < 4; mt++)
#pragma unroll
        for (int nt = 0; nt < 4; nt++)
#pragma unroll
            for (int i = 0; i < 4; i++) c[mt][nt][i] = 0.f;

    const int nid_a = nid_s[trow];
    const float* arow_mem = &memv[(size_t)nid_a * 128];
    const float* arow_feat = &feat[(size_t)nid_a * 128];
    const __half* brow = &Wt[(size_t)trow * 256 + tkh * 8];

    float apre[8];
    uint4 bpre;
    auto load_a = [&](int ch, float* ap) {
        int col = ch * 16 + tkh * 8;
        const float* srcrow = (col < 128) ? (arow_mem + col) : (arow_feat + col - 128);
        float4 v0 = *(const float4*)srcrow;
        float4 v1 = *(const float4*)(srcrow + 4);
        ap[0] = v0.x; ap[1] = v0.y; ap[2] = v0.z; ap[3] = v0.w;
        ap[4] = v1.x; ap[5] = v1.y; ap[6] = v1.z; ap[7] = v1.w;
    };
    auto load_b = [&](int ch) { bpre = *(const uint4*)(brow + ch * 16); };
    auto store_ab = [&](int buf, const float* ap) {
        uint4 pa;
        pa.x = pkh2(ap[0], ap[1]); pa.y = pkh2(ap[2], ap[3]);
        pa.z = pkh2(ap[4], ap[5]); pa.w = pkh2(ap[6], ap[7]);
        *(uint4*)&As[buf][tkh * 1024 + trow * 8] = pa;
        *(uint4*)&Bs[buf][tkh * 1024 + trow * 8] = bpre;
    };

    load_a(0, apre); load_b(0);
    store_ab(0, apre);
    __syncthreads();

    for (int ch = 0; ch < 16; ch++) {
        int buf = ch & 1;
        if (ch < 15) { load_a(ch + 1, apre); load_b(ch + 1); }
        gemm_compute16((const unsigned*)As[buf], (const unsigned*)Bs[buf],
                       row_base, col_base, lr, lc, c);
        if (ch < 15) {
            store_ab(buf ^ 1, apre);
            __syncthreads();
        }
    }

#pragma unroll
    for (int nt = 0; nt < 4; nt++) {
        int col = col_base + nt * 8 + lc * 2;
        float2 bb = *(const float2*)&bias[col];
#pragma unroll
        for (int mt = 0; mt < 4; mt++) {
            int r0 = row_base + mt * 16 + lr;
            if (r0 < rows)
                *(unsigned*)&g_yh[(size_t)(m0 + r0) * 512 + which * 128 + col] =
                    pkh2(c[mt][nt][0] + bb.x, c[mt][nt][1] + bb.y);
            if (r0 + 8 < rows)
                *(unsigned*)&g_yh[(size_t)(m0 + r0 + 8) * 512 + which * 128 + col] =
                    pkh2(c[mt][nt][2] + bb.x, c[mt][nt][3] + bb.y);
        }
    }
}

// ---------------- edge GEMM ----------------------------------------------------
__global__ __launch_bounds__(256, 2) void k_edge_gemm(const int* __restrict__ src_a,
                                                      const int* __restrict__ e_id,
                                                      const float* __restrict__ edge_t,
                                                      const float* __restrict__ eraw,
                                                      const float* __restrict__ w_t,
                                                      const float* __restrict__ b_t) {
    __shared__ __half As[2][TBUF];
    __shared__ __half Bs[2][TBUF];
    __shared__ float relt_s[128];
    __shared__ int eid_s[128];
    const int m0 = blockIdx.x * 128;
    const int tid = threadIdx.x;
    int rows = ME - m0; if (rows > 128) rows = 128;
    if (tid < 128) {
        int r = (tid < rows ? tid : rows - 1);
        int e = e_id[m0 + r];
        eid_s[tid] = e;
        relt_s[tid] = edge_t[e] - g_lu[src_a[m0 + r]];
    }
    __syncthreads();

    const int warp = tid >> 5, lane = tid & 31;
    const int wm = warp & 1, wn = warp >> 1;
    const int row_base = wm * 64, col_base = wn * 32;
    const int lr = lane >> 2, lc = lane & 3;
    const int trow = tid & 127, tkh = tid >> 7;

    float c[4][4][4];
#pragma unroll
    for (int mt = 0; mt < 4; mt++)
#pragma unroll
        for (int nt = 0; nt < 4; nt++)
#pragma unroll
            for (int i = 0; i < 4; i++) c[mt][nt][i] = 0.f;

    const float rt_a = relt_s[trow];
    const float* arow_msg = &eraw[(size_t)eid_s[trow] * 128];
    const __half* brow = &g_wT[(size_t)4 * 32768 + (size_t)trow * 256 + tkh * 8];

    float apre[8];
    uint4 bpre;
    auto load_a = [&](int ch, float* ap) {
        int col = ch * 16 + tkh * 8;
        if (col < 128) {
            float4 w0 = *(const float4*)&w_t[col];
            float4 w1 = *(const float4*)&w_t[col + 4];
            float4 bt0 = *(const float4*)&b_t[col];
            float4 bt1 = *(const float4*)&b_t[col + 4];
            ap[0] = fast_cos(fmaf(rt_a, w0.x, bt0.x));
            ap[1] = fast_cos(fmaf(rt_a, w0.y, bt0.y));
            ap[2] = fast_cos(fmaf(rt_a, w0.z, bt0.z));
            ap[3] = fast_cos(fmaf(rt_a, w0.w, bt0.w));
            ap[4] = fast_cos(fmaf(rt_a, w1.x, bt1.x));
            ap[5] = fast_cos(fmaf(rt_a, w1.y, bt1.y));
            ap[6] = fast_cos(fmaf(rt_a, w1.z, bt1.z));
            ap[7] = fast_cos(fmaf(rt_a, w1.w, bt1.w));
        } else {
            const float* srcrow = arow_msg + (col - 128);
            float4 v0 = *(const float4*)srcrow;
            float4 v1 = *(const float4*)(srcrow + 4);
            ap[0] = v0.x; ap[1] = v0.y; ap[2] = v0.z; ap[3] = v0.w;
            ap[4] = v1.x; ap[5] = v1.y; ap[6] = v1.z; ap[7] = v1.w;
        }
    };
    auto load_b = [&](int ch) { bpre = *(const uint4*)(brow + ch * 16); };
    auto store_ab = [&](int buf, const float* ap) {
        uint4 pa;
        pa.x = pkh2(ap[0], ap[1]); pa.y = pkh2(ap[2], ap[3]);
        pa.z = pkh2(ap[4], ap[5]); pa.w = pkh2(ap[6], ap[7]);
        *(uint4*)&As[buf][tkh * 1024 + trow * 8] = pa;
        *(uint4*)&Bs[buf][tkh * 1024 + trow * 8] = bpre;
    };

    load_a(0, apre); load_b(0);
    store_ab(0, apre);
    __syncthreads();

    for (int ch = 0; ch < 16; ch++) {
        int buf = ch & 1;
        if (ch < 15) { load_a(ch + 1, apre); load_b(ch + 1); }
        gemm_compute16((const unsigned*)As[buf], (const unsigned*)Bs[buf],
                       row_base, col_base, lr, lc, c);
        if (ch < 15) {
            store_ab(buf ^ 1, apre);
            __syncthreads();
        }
    }

#pragma unroll
    for (int nt = 0; nt < 4; nt++) {
        int col = col_base + nt * 8 + lc * 2;
#pragma unroll
        for (int mt = 0; mt < 4; mt++) {
            int r0 = row_base + mt * 16 + lr;
            if (r0 < rows)
                *(unsigned*)&g_eh[(size_t)(m0 + r0) * 128 + col] =
                    pkh2(c[mt][nt][0], c[mt][nt][1]);
            if (r0 + 8 < rows)
                *(unsigned*)&g_eh[(size_t)(m0 + r0 + 8) * 128 + col] =
                    pkh2(c[mt][nt][2], c[mt][nt][3]);
        }
    }
}

// ---------------- fused attention (fp16 inputs, fp32 math/accum) ------------
__global__ __launch_bounds__(256) void k_attn(const int* __restrict__ src_a,
                                              const int* __restrict__ dst_a,
                                              float* __restrict__ out) {
    int gw = (blockIdx.x * 256 + threadIdx.x) >> 5;
    int lane = threadIdx.x & 31;
    if (gw >= ME) return;
    int s = src_a[gw], d = dst_a[gw];
    uint2 qu = *(const uint2*)&g_yh[(size_t)d * 512 + lane * 4];
    uint2 ku = *(const uint2*)&g_yh[(size_t)s * 512 + 128 + lane * 4];
    uint2 vu = *(const uint2*)&g_yh[(size_t)s * 512 + 256 + lane * 4];
    uint2 eu = *(const uint2*)&g_eh[(size_t)gw * 128 + lane * 4];
    float2 q0 = uph2(qu.x), q1 = uph2(qu.y);
    float2 k0 = uph2(ku.x), k1 = uph2(ku.y);
    float2 v0 = uph2(vu.x), v1 = uph2(vu.y);
    float2 e0 = uph2(eu.x), e1 = uph2(eu.y);
    float ke0x = k0.x + e0.x, ke0y = k0.y + e0.y, ke1x = k1.x + e1.x, ke1y = k1.y + e1.y;
    float p = q0.x * ke0x + q0.y * ke0y + q1.x * ke1x + q1.y * ke1y;
    p += __shfl_xor_sync(0xffffffffu, p, 8);
    p += __shfl_xor_sync(0xffffffffu, p, 4);
    p += __shfl_xor_sync(0xffffffffu, p, 2);
    p += __shfl_xor_sync(0xffffffffu, p, 1);
    float alpha = __expf(p * 0.125f);   // 1/sqrt(64)
    if ((lane & 15) == 0) atomicAdd(&g_denom[d * 2 + (lane >> 4)], alpha);
    float4 o = make_float4(alpha * (v0.x + e0.x), alpha * (v0.y + e0.y),
                           alpha * (v1.x + e1.x), alpha * (v1.y + e1.y));
    float* dptr = &out[(size_t)d * 128 + lane * 4];
    asm volatile("red.global.add.v4.f32 [%0], {%1,%2,%3,%4};"
                 :: "l"(dptr), "f"(o.x), "f"(o.y), "f"(o.z), "f"(o.w) : "memory");
}

// ---------------- finalize: out = out/denom + skip --------------------------
__global__ void k_final(float* __restrict__ out) {
    int i = blockIdx.x * 256 + threadIdx.x;
    if (i >= KN * 32) return;
    int node = i >> 5;
    int j4 = (i & 31) * 4;
    int h = j4 >> 6;
    float den = g_denom[node * 2 + h];
    float inv = den > 0.f ? 1.f / den : 0.f;
    float4 u = *(float4*)&out[(size_t)node * 128 + j4];
    uint2 sku = *(const uint2*)&g_yh[(size_t)node * 512 + 384 + j4];
    float2 s0 = uph2(sku.x), s1 = uph2(sku.y);
    u.x = u.x * inv + s0.x;
    u.y = u.y * inv + s0.y;
    u.z = u.z * inv + s1.x;
    u.w = u.w * inv + s1.y;
    *(float4*)&out[(size_t)node * 128 + j4] = u;
}

// ---------------- launch -----------------------------------------------------
extern "C" void kernel_launch(void* const* d_in, const int* in_sizes, int n_in,
                              void* d_out, int out_size) {
    (void)in_sizes; (void)n_in; (void)out_size;
    const int*   n_id    = (const int*)d_in[0];
    const int*   eib     = (const int*)d_in[1];   // [2, M]: src then dst
    const int*   e_id    = (const int*)d_in[2];
    const float* nfeat   = (const float*)d_in[4];
    const float* eraw    = (const float*)d_in[5];
    const float* edge_t  = (const float*)d_in[6];
    const float* memv    = (const float*)d_in[7];
    const float* last_up = (const float*)d_in[8];
    const float* w_t     = (const float*)d_in[9];
    const float* b_t     = (const float*)d_in[10];
    const float* Wq = (const float*)d_in[11];
    const float* Wk = (const float*)d_in[13];
    const float* Wv = (const float*)d_in[15];
    const float* We = (const float*)d_in[17];
    const float* Wskip = (const float*)d_in[18];
    NodeB pb;
    pb.b[0] = (const float*)d_in[12];
    pb.b[1] = (const float*)d_in[14];
    pb.b[2] = (const float*)d_in[16];
    pb.b[3] = (const float*)d_in[19];
    float* out = (float*)d_out;

    k_prep<<<(5 * 32768 + 255) / 256, 256>>>(Wq, Wk, Wv, Wskip, We);
    k_init<<<(KN * 128 + 255) / 256, 256>>>(out, last_up, n_id);
    dim3 gn(4, (KN + 127) / 128);
    k_node_gemm<<<gn, 256>>>(n_id, memv, nfeat, pb);
    k_edge_gemm<<<(ME + 127) / 128, 256>>>(eib, e_id, edge_t, eraw, w_t, b_t);
    k_attn<<<ME / 8, 256>>>(eib, eib + ME, out);
    k_final<<<(KN * 32 + 255) / 256, 256>>>(out);
}